// round 14
// baseline (speedup 1.0000x reference)
#include <cuda_runtime.h>
#include <cuda_fp16.h>

// Problem constants (from reference): L=131072, D=512, B=512, S=512
#define LQ 131072
#define DQ 512
#define SQ 512
#define CAP 24          // slots per label row; Poisson(2) => P(cnt>24) ~ 1e-18

#define SCORE_BLOCKS 888            // 148 SMs x 6 resident blocks
#define TOTAL_WARPS (SCORE_BLOCKS * 8)

// ---- static scratch (no runtime allocation; zero-initialized at load) ----
// g_count is SELF-CLEANING: score_kernel resets each row to 0 after reading,
// so every kernel_launch invocation (and every graph replay) starts from zeros.
__device__ int    g_count[LQ];                // refs per label
__device__ int    g_slots[(size_t)LQ * CAP];  // packed (b<<16)|s per label
__device__ __half g_Xh   [512 * DQ];          // fp16 input rows (512 KB, L2-resident)
__device__ float  g_sa   [DQ];                // sigmoid(alpha)
__device__ float  g_sb   [DQ];                // sigmoid(beta)

// ---------------------------------------------------------------------------
// dtype detection (shortlist may be int32 or int64; true indices < 2^17 so
// int64 high words are all zero; int32 packing puts a random index there)
// ---------------------------------------------------------------------------
__device__ __forceinline__ bool detect_is32(const void* sl, int lane) {
    const unsigned long long* slu = (const unsigned long long*)sl;
    unsigned int hi = (unsigned int)(slu[lane] >> 32);
    hi = __reduce_or_sync(0xffffffffu, hi);
    return hi != 0u;
}

// ---------------------------------------------------------------------------
// Kernel A (prep): blocks [0,1024) bucket the shortlist into per-label slots;
// blocks [1024,1152) build sigmoid LUTs + fp16 input rows.
// ---------------------------------------------------------------------------
__global__ __launch_bounds__(256)
void prep_kernel(const void* __restrict__ shortlist,
                 const float* __restrict__ input,
                 const float* __restrict__ alpha,
                 const float* __restrict__ beta) {
    const int bid = blockIdx.x;
    if (bid < 1024) {
        const int lane = threadIdx.x & 31;
        const bool is32 = detect_is32(shortlist, lane);
        const int t = bid * 256 + threadIdx.x;       // flat = b*SQ + s
        const int idx = is32 ? ((const int*)shortlist)[t]
                             : (int)((const long long*)shortlist)[t];
        const int pair = ((t >> 9) << 16) | (t & (SQ - 1)); // (b<<16)|s
        const int pos = atomicAdd(&g_count[idx], 1);
        if (pos < CAP)
            g_slots[(size_t)idx * CAP + pos] = pair;
        // cnt > CAP rows are recomputed from the shortlist in score_kernel.
        return;
    }
    const int t = (bid - 1024) * 256 + threadIdx.x;  // 32768 threads
    if (t < DQ) {
        g_sa[t] = 1.0f / (1.0f + __expf(-alpha[t]));
        g_sb[t] = 1.0f / (1.0f + __expf(-beta[t]));
    }
    const long long base = (long long)t * 8;         // 8 floats -> 8 halfs
    const float4* x4 = reinterpret_cast<const float4*>(input + base);
    float4 a = x4[0], b = x4[1];
    __half2 h0 = __floats2half2_rn(a.x, a.y);
    __half2 h1 = __floats2half2_rn(a.z, a.w);
    __half2 h2 = __floats2half2_rn(b.x, b.y);
    __half2 h3 = __floats2half2_rn(b.z, b.w);
    uint4 o;
    o.x = *reinterpret_cast<unsigned int*>(&h0);
    o.y = *reinterpret_cast<unsigned int*>(&h1);
    o.z = *reinterpret_cast<unsigned int*>(&h2);
    o.w = *reinterpret_cast<unsigned int*>(&h3);
    reinterpret_cast<uint4*>(g_Xh)[t] = o;
}

// ---------------------------------------------------------------------------
// Kernel B (score): PERSISTENT warps. Each warp loops over ~18 label rows
// (stride = total warp count) so Poisson imbalance averages out and warp
// slots stay full. Per row: stream W,V once (HBM, evict-first), fold sigmoids
// into a register-resident combined row, push dots to referencing samples
// (fp16 input rows from L1/L2). Self-cleans g_count.
//
// Element layout: lane owns elements [8*lane, 8*lane+8) and
// [8*lane+256, 8*lane+264). Xh loads are uint4 (8 halfs) at unit indices
// {lane, lane+32}; c registers are built from W/V float4 indices
// {2*lane, 2*lane+1, 2*lane+64, 2*lane+65} to match EXACTLY.
// ---------------------------------------------------------------------------
__device__ __forceinline__ float dot8h(uint4 u, float4 ca, float4 cb) {
    __half2 h0 = *reinterpret_cast<__half2*>(&u.x);
    __half2 h1 = *reinterpret_cast<__half2*>(&u.y);
    __half2 h2 = *reinterpret_cast<__half2*>(&u.z);
    __half2 h3 = *reinterpret_cast<__half2*>(&u.w);
    float2 f0 = __half22float2(h0), f1 = __half22float2(h1);
    float2 f2 = __half22float2(h2), f3 = __half22float2(h3);
    float acc;
    acc  = f0.x * ca.x + f0.y * ca.y + f1.x * ca.z + f1.y * ca.w;
    acc += f2.x * cb.x + f2.y * cb.y + f3.x * cb.z + f3.y * cb.w;
    return acc;
}

__global__ __launch_bounds__(256, 6)
void score_kernel(const float* __restrict__ W,       // weight [L, D]
                  const float* __restrict__ V,       // labels [L, D]
                  const float* __restrict__ bias,    // [L]
                  const void*  __restrict__ shortlist,
                  float* __restrict__ out)           // [B, S]
{
    const int gwarp = blockIdx.x * 8 + (threadIdx.x >> 5);
    const int lane  = threadIdx.x & 31;

    const float4* sa4 = reinterpret_cast<const float4*>(g_sa);
    const float4* sb4 = reinterpret_cast<const float4*>(g_sb);

    // float4 indices owned by this lane (elements [8*lane,+8) and [8*lane+256,+8))
    const int i0 = 2 * lane;       // elements [8*lane,     8*lane+4)
    const int i1 = 2 * lane + 1;   // elements [8*lane+4,   8*lane+8)
    const int i2 = 2 * lane + 64;  // elements [8*lane+256, 8*lane+260)
    const int i3 = 2 * lane + 65;  // elements [8*lane+260, 8*lane+264)

    for (int row = gwarp; row < LQ; row += TOTAL_WARPS) {
        const int cnt = g_count[row];
        if (lane == 0 && cnt != 0) g_count[row] = 0;   // self-clean
        if (cnt == 0) continue;

        const int* slots = g_slots + (size_t)row * CAP;

        // Hoist first pair words: independent of the W/V DRAM stream, so the
        // pair -> Xh chain overlaps the long row fetch.
        int p0 = slots[0];
        int p1 = (cnt > 1) ? slots[1] : 0;

        const float4* w4 = reinterpret_cast<const float4*>(W + (size_t)row * DQ);
        const float4* v4 = reinterpret_cast<const float4*>(V + (size_t)row * DQ);

        // W/V are read-once -> __ldcs (evict-first). Interleave with L1-hit
        // LUT loads to avoid one long front-batched LDG run.
        float4 w0 = __ldcs(w4 + i0);
        float4 w1 = __ldcs(w4 + i1);
        float4 w2 = __ldcs(w4 + i2);
        float4 w3 = __ldcs(w4 + i3);
        float4 a0 = sa4[i0], a1 = sa4[i1], a2 = sa4[i2], a3 = sa4[i3];
        float4 v0 = __ldcs(v4 + i0);
        float4 v1 = __ldcs(v4 + i1);
        float4 v2 = __ldcs(v4 + i2);
        float4 v3 = __ldcs(v4 + i3);
        float4 b0 = sb4[i0], b1 = sb4[i1], b2 = sb4[i2], b3 = sb4[i3];

        float4 c0 = make_float4(a0.x*w0.x + b0.x*v0.x, a0.y*w0.y + b0.y*v0.y,
                                a0.z*w0.z + b0.z*v0.z, a0.w*w0.w + b0.w*v0.w);
        float4 c1 = make_float4(a1.x*w1.x + b1.x*v1.x, a1.y*w1.y + b1.y*v1.y,
                                a1.z*w1.z + b1.z*v1.z, a1.w*w1.w + b1.w*v1.w);
        float4 c2 = make_float4(a2.x*w2.x + b2.x*v2.x, a2.y*w2.y + b2.y*v2.y,
                                a2.z*w2.z + b2.z*v2.z, a2.w*w2.w + b2.w*v2.w);
        float4 c3 = make_float4(a3.x*w3.x + b3.x*v3.x, a3.y*w3.y + b3.y*v3.y,
                                a3.z*w3.z + b3.z*v3.z, a3.w*w3.w + b3.w*v3.w);

        const float bs = bias[row];

        if (cnt <= CAP) {
            int i = 0;
            for (; i + 2 <= cnt; i += 2) {
                const int b0i = p0 >> 16, s0 = p0 & 0xffff;
                const int b1i = p1 >> 16, s1 = p1 & 0xffff;
                const uint4* x0 = reinterpret_cast<const uint4*>(g_Xh + (size_t)b0i * DQ);
                const uint4* x1 = reinterpret_cast<const uint4*>(g_Xh + (size_t)b1i * DQ);

                uint4 u00 = x0[lane], u01 = x0[lane + 32];
                uint4 u10 = x1[lane], u11 = x1[lane + 32];

                if (i + 2 < cnt) {                   // prefetch next pair words
                    p0 = slots[i + 2];
                    p1 = (i + 3 < cnt) ? slots[i + 3] : 0;
                }

                float r0 = dot8h(u00, c0, c1) + dot8h(u01, c2, c3);
                float r1 = dot8h(u10, c0, c1) + dot8h(u11, c2, c3);

                #pragma unroll
                for (int o = 16; o > 0; o >>= 1) {
                    r0 += __shfl_xor_sync(0xffffffffu, r0, o);
                    r1 += __shfl_xor_sync(0xffffffffu, r1, o);
                }
                if (lane == 0) {
                    out[b0i * SQ + s0] = r0 + bs;
                    out[b1i * SQ + s1] = r1 + bs;
                }
            }
            if (i < cnt) {
                const int b0i = p0 >> 16, s0 = p0 & 0xffff;
                const uint4* x0 = reinterpret_cast<const uint4*>(g_Xh + (size_t)b0i * DQ);
                uint4 u00 = x0[lane], u01 = x0[lane + 32];
                float r0 = dot8h(u00, c0, c1) + dot8h(u01, c2, c3);
                #pragma unroll
                for (int o = 16; o > 0; o >>= 1)
                    r0 += __shfl_xor_sync(0xffffffffu, r0, o);
                if (lane == 0)
                    out[b0i * SQ + s0] = r0 + bs;
            }
        } else {
            // Overflow safety net (statistically never taken): the stored slot
            // subset is nondeterministic, so recompute ALL refs of this row by
            // rescanning the shortlist. Each ref's output is independent.
            const bool is32 = detect_is32(shortlist, lane);
            const int*       sl32 = (const int*)shortlist;
            const long long* sl64 = (const long long*)shortlist;
            #pragma unroll 1
            for (int t = 0; t < 512 * SQ; t++) {
                const int idx = is32 ? sl32[t] : (int)sl64[t];
                if (idx != row) continue;
                const int b0i = t >> 9, s0 = t & (SQ - 1);
                const uint4* x0 = reinterpret_cast<const uint4*>(g_Xh + (size_t)b0i * DQ);
                uint4 u00 = x0[lane], u01 = x0[lane + 32];
                float r0 = dot8h(u00, c0, c1) + dot8h(u01, c2, c3);
                #pragma unroll
                for (int o = 16; o > 0; o >>= 1)
                    r0 += __shfl_xor_sync(0xffffffffu, r0, o);
                if (lane == 0)
                    out[b0i * SQ + s0] = r0 + bs;
            }
        }
    }
}

extern "C" void kernel_launch(void* const* d_in, const int* in_sizes, int n_in,
                              void* d_out, int out_size) {
    const float* input     = (const float*)d_in[0];      // [B, D]
    const float* labels    = (const float*)d_in[1];      // [L, D]  (v)
    const float* weight    = (const float*)d_in[2];      // [L, D]  (u)
    const float* alpha     = (const float*)d_in[3];      // [1, D]
    const float* beta      = (const float*)d_in[4];      // [1, D]
    const float* bias      = (const float*)d_in[5];      // [L]
    const void*  shortlist = d_in[6];                    // [B, S] int32 or int64
    float*       out       = (float*)d_out;              // [B, S]

    prep_kernel<<<1152, 256>>>(shortlist, input, alpha, beta);
    score_kernel<<<SCORE_BLOCKS, 256>>>(weight, labels, bias, shortlist, out);
}

// round 16
// speedup vs baseline: 1.0489x; 1.0489x over previous
#include <cuda_runtime.h>
#include <cuda_fp16.h>

// Problem constants (from reference): L=131072, D=512, B=512, S=512
#define LQ 131072
#define DQ 512
#define SQ 512
#define CAP 24          // slots per label row; Poisson(2) => P(cnt>24) ~ 1e-18

#define SCORE_BLOCKS 888            // 148 SMs x 6 resident blocks
#define TOTAL_WARPS (SCORE_BLOCKS * 8)

// ---- static scratch (no runtime allocation; zero-initialized at load) ----
// g_count is SELF-CLEANING: score_kernel resets each row to 0 after reading,
// so every kernel_launch invocation (and every graph replay) starts from zeros.
__device__ int    g_count[LQ];                // refs per label
__device__ int    g_slots[(size_t)LQ * CAP];  // packed (b<<16)|s per label
__device__ __half g_Xh   [512 * DQ];          // fp16 input rows (512 KB, L2-resident)
__device__ float  g_sa   [DQ];                // sigmoid(alpha)
__device__ float  g_sb   [DQ];                // sigmoid(beta)

// ---------------------------------------------------------------------------
// dtype detection (shortlist may be int32 or int64; true indices < 2^17 so
// int64 high words are all zero; int32 packing puts a random index there)
// ---------------------------------------------------------------------------
__device__ __forceinline__ bool detect_is32(const void* sl, int lane) {
    const unsigned long long* slu = (const unsigned long long*)sl;
    unsigned int hi = (unsigned int)(slu[lane] >> 32);
    hi = __reduce_or_sync(0xffffffffu, hi);
    return hi != 0u;
}

// ---------------------------------------------------------------------------
// Kernel A (prep): blocks [0,1024) bucket the shortlist into per-label slots;
// blocks [1024,1152) build sigmoid LUTs + fp16 input rows.
// ---------------------------------------------------------------------------
__global__ __launch_bounds__(256)
void prep_kernel(const void* __restrict__ shortlist,
                 const float* __restrict__ input,
                 const float* __restrict__ alpha,
                 const float* __restrict__ beta) {
    const int bid = blockIdx.x;
    if (bid < 1024) {
        const int lane = threadIdx.x & 31;
        const bool is32 = detect_is32(shortlist, lane);
        const int t = bid * 256 + threadIdx.x;       // flat = b*SQ + s
        const int idx = is32 ? ((const int*)shortlist)[t]
                             : (int)((const long long*)shortlist)[t];
        const int pair = ((t >> 9) << 16) | (t & (SQ - 1)); // (b<<16)|s
        const int pos = atomicAdd(&g_count[idx], 1);
        if (pos < CAP)
            g_slots[(size_t)idx * CAP + pos] = pair;
        // cnt > CAP rows are recomputed from the shortlist in score_kernel.
        return;
    }
    const int t = (bid - 1024) * 256 + threadIdx.x;  // 32768 threads
    if (t < DQ) {
        g_sa[t] = 1.0f / (1.0f + __expf(-alpha[t]));
        g_sb[t] = 1.0f / (1.0f + __expf(-beta[t]));
    }
    const long long base = (long long)t * 8;         // 8 floats -> 8 halfs
    const float4* x4 = reinterpret_cast<const float4*>(input + base);
    float4 a = x4[0], b = x4[1];
    __half2 h0 = __floats2half2_rn(a.x, a.y);
    __half2 h1 = __floats2half2_rn(a.z, a.w);
    __half2 h2 = __floats2half2_rn(b.x, b.y);
    __half2 h3 = __floats2half2_rn(b.z, b.w);
    uint4 o;
    o.x = *reinterpret_cast<unsigned int*>(&h0);
    o.y = *reinterpret_cast<unsigned int*>(&h1);
    o.z = *reinterpret_cast<unsigned int*>(&h2);
    o.w = *reinterpret_cast<unsigned int*>(&h3);
    reinterpret_cast<uint4*>(g_Xh)[t] = o;
}

// ---------------------------------------------------------------------------
// Kernel B (score): PERSISTENT warps (occupancy/imbalance win from R13) with
// the R11 memory layout (warp-contiguous per-instruction addressing: every
// LDG covers a contiguous span -> minimal L1tex wavefronts).
// Lane owns float4/uint2 unit indices {lane, lane+32, lane+64, lane+96}:
// elements [4*lane+128k, 4*lane+128k+4). c registers and Xh loads pair 1:1.
// ---------------------------------------------------------------------------
__device__ __forceinline__ float dot4h(uint2 u, float4 c) {
    __half2 h0 = *reinterpret_cast<__half2*>(&u.x);
    __half2 h1 = *reinterpret_cast<__half2*>(&u.y);
    float2 f0 = __half22float2(h0), f1 = __half22float2(h1);
    return f0.x * c.x + f0.y * c.y + f1.x * c.z + f1.y * c.w;
}

__global__ __launch_bounds__(256, 6)
void score_kernel(const float* __restrict__ W,       // weight [L, D]
                  const float* __restrict__ V,       // labels [L, D]
                  const float* __restrict__ bias,    // [L]
                  const void*  __restrict__ shortlist,
                  float* __restrict__ out)           // [B, S]
{
    const int gwarp = blockIdx.x * 8 + (threadIdx.x >> 5);
    const int lane  = threadIdx.x & 31;

    const float4* sa4 = reinterpret_cast<const float4*>(g_sa);
    const float4* sb4 = reinterpret_cast<const float4*>(g_sb);

    for (int row = gwarp; row < LQ; row += TOTAL_WARPS) {
        const int cnt = g_count[row];
        if (lane == 0 && cnt != 0) g_count[row] = 0;   // self-clean
        if (cnt == 0) continue;

        const int* slots = g_slots + (size_t)row * CAP;

        // Hoist first pair words: independent of the W/V DRAM stream, so the
        // pair -> Xh chain overlaps the long row fetch.
        int p0 = slots[0];
        int p1 = (cnt > 1) ? slots[1] : 0;

        const float4* w4 = reinterpret_cast<const float4*>(W + (size_t)row * DQ);
        const float4* v4 = reinterpret_cast<const float4*>(V + (size_t)row * DQ);

        // W/V are read-once -> __ldcs (evict-first). Warp-contiguous stride:
        // each LDG.128 covers one contiguous 512B span (4 lines, min wavefronts).
        float4 w0 = __ldcs(w4 + lane);
        float4 w1 = __ldcs(w4 + lane + 32);
        float4 w2 = __ldcs(w4 + lane + 64);
        float4 w3 = __ldcs(w4 + lane + 96);
        float4 a0 = sa4[lane], a1 = sa4[lane + 32], a2 = sa4[lane + 64], a3 = sa4[lane + 96];
        float4 v0 = __ldcs(v4 + lane);
        float4 v1 = __ldcs(v4 + lane + 32);
        float4 v2 = __ldcs(v4 + lane + 64);
        float4 v3 = __ldcs(v4 + lane + 96);
        float4 b0 = sb4[lane], b1 = sb4[lane + 32], b2 = sb4[lane + 64], b3 = sb4[lane + 96];

        float4 c0 = make_float4(a0.x*w0.x + b0.x*v0.x, a0.y*w0.y + b0.y*v0.y,
                                a0.z*w0.z + b0.z*v0.z, a0.w*w0.w + b0.w*v0.w);
        float4 c1 = make_float4(a1.x*w1.x + b1.x*v1.x, a1.y*w1.y + b1.y*v1.y,
                                a1.z*w1.z + b1.z*v1.z, a1.w*w1.w + b1.w*v1.w);
        float4 c2 = make_float4(a2.x*w2.x + b2.x*v2.x, a2.y*w2.y + b2.y*v2.y,
                                a2.z*w2.z + b2.z*v2.z, a2.w*w2.w + b2.w*v2.w);
        float4 c3 = make_float4(a3.x*w3.x + b3.x*v3.x, a3.y*w3.y + b3.y*v3.y,
                                a3.z*w3.z + b3.z*v3.z, a3.w*w3.w + b3.w*v3.w);

        const float bs = bias[row];

        if (cnt <= CAP) {
            int i = 0;
            for (; i + 2 <= cnt; i += 2) {
                const int b0i = p0 >> 16, s0 = p0 & 0xffff;
                const int b1i = p1 >> 16, s1 = p1 & 0xffff;
                const uint2* x0 = reinterpret_cast<const uint2*>(g_Xh + (size_t)b0i * DQ);
                const uint2* x1 = reinterpret_cast<const uint2*>(g_Xh + (size_t)b1i * DQ);

                uint2 u00 = x0[lane], u01 = x0[lane + 32], u02 = x0[lane + 64], u03 = x0[lane + 96];
                uint2 u10 = x1[lane], u11 = x1[lane + 32], u12 = x1[lane + 64], u13 = x1[lane + 96];

                if (i + 2 < cnt) {                   // prefetch next pair words
                    p0 = slots[i + 2];
                    p1 = (i + 3 < cnt) ? slots[i + 3] : 0;
                }

                float r0 = dot4h(u00, c0) + dot4h(u01, c1) + dot4h(u02, c2) + dot4h(u03, c3);
                float r1 = dot4h(u10, c0) + dot4h(u11, c1) + dot4h(u12, c2) + dot4h(u13, c3);

                #pragma unroll
                for (int o = 16; o > 0; o >>= 1) {
                    r0 += __shfl_xor_sync(0xffffffffu, r0, o);
                    r1 += __shfl_xor_sync(0xffffffffu, r1, o);
                }
                if (lane == 0) {
                    out[b0i * SQ + s0] = r0 + bs;
                    out[b1i * SQ + s1] = r1 + bs;
                }
            }
            if (i < cnt) {
                const int b0i = p0 >> 16, s0 = p0 & 0xffff;
                const uint2* x0 = reinterpret_cast<const uint2*>(g_Xh + (size_t)b0i * DQ);
                uint2 u00 = x0[lane], u01 = x0[lane + 32], u02 = x0[lane + 64], u03 = x0[lane + 96];
                float r0 = dot4h(u00, c0) + dot4h(u01, c1) + dot4h(u02, c2) + dot4h(u03, c3);
                #pragma unroll
                for (int o = 16; o > 0; o >>= 1)
                    r0 += __shfl_xor_sync(0xffffffffu, r0, o);
                if (lane == 0)
                    out[b0i * SQ + s0] = r0 + bs;
            }
        } else {
            // Overflow safety net (statistically never taken): the stored slot
            // subset is nondeterministic, so recompute ALL refs of this row by
            // rescanning the shortlist. Each ref's output is independent.
            const bool is32 = detect_is32(shortlist, lane);
            const int*       sl32 = (const int*)shortlist;
            const long long* sl64 = (const long long*)shortlist;
            #pragma unroll 1
            for (int t = 0; t < 512 * SQ; t++) {
                const int idx = is32 ? sl32[t] : (int)sl64[t];
                if (idx != row) continue;
                const int b0i = t >> 9, s0 = t & (SQ - 1);
                const uint2* x0 = reinterpret_cast<const uint2*>(g_Xh + (size_t)b0i * DQ);
                uint2 u00 = x0[lane], u01 = x0[lane + 32], u02 = x0[lane + 64], u03 = x0[lane + 96];
                float r0 = dot4h(u00, c0) + dot4h(u01, c1) + dot4h(u02, c2) + dot4h(u03, c3);
                #pragma unroll
                for (int o = 16; o > 0; o >>= 1)
                    r0 += __shfl_xor_sync(0xffffffffu, r0, o);
                if (lane == 0)
                    out[b0i * SQ + s0] = r0 + bs;
            }
        }
    }
}

extern "C" void kernel_launch(void* const* d_in, const int* in_sizes, int n_in,
                              void* d_out, int out_size) {
    const float* input     = (const float*)d_in[0];      // [B, D]
    const float* labels    = (const float*)d_in[1];      // [L, D]  (v)
    const float* weight    = (const float*)d_in[2];      // [L, D]  (u)
    const float* alpha     = (const float*)d_in[3];      // [1, D]
    const float* beta      = (const float*)d_in[4];      // [1, D]
    const float* bias      = (const float*)d_in[5];      // [L]
    const void*  shortlist = d_in[6];                    // [B, S] int32 or int64
    float*       out       = (float*)d_out;              // [B, S]

    prep_kernel<<<1152, 256>>>(shortlist, input, alpha, beta);
    score_kernel<<<SCORE_BLOCKS, 256>>>(weight, labels, bias, shortlist, out);
}